// round 1
// baseline (speedup 1.0000x reference)
#include <cuda_runtime.h>

#define BATCH      8192
#define NF         39
#define ED         64
#define ED4        (ED/4)
#define RANK       32
#define NTHREADS   256

// smem W layouts padded to 40 floats per rank-row
#define NFP 40

__global__ __launch_bounds__(NTHREADS, 6)
void tfm_kernel(const int*   __restrict__ x,
                const float* __restrict__ table,
                const float* __restrict__ lw,
                const float* __restrict__ lb,
                const float* __restrict__ W0,
                const float* __restrict__ W1,
                float*       __restrict__ out)
{
    __shared__ float4 emb[NF][ED4];          // 39*16*16B = 9984 B
    __shared__ float  w0s[2][RANK][NFP];     // 10240 B
    __shared__ float  w1s[3][RANK][NFP];     // 15360 B
    __shared__ int    idx[NF];
    __shared__ float  red[NTHREADS / 32];

    const int b   = blockIdx.x;
    const int tid = threadIdx.x;

    // ---- stage indices + weights into smem ----
    if (tid < NF) idx[tid] = x[b * NF + tid];

    for (int t = tid; t < 2 * RANK * NF; t += NTHREADS) {
        int l = t / (RANK * NF);
        int r = t % (RANK * NF);
        w0s[l][r / NF][r % NF] = W0[t];
    }
    for (int t = tid; t < 3 * RANK * NF; t += NTHREADS) {
        int l = t / (RANK * NF);
        int r = t % (RANK * NF);
        w1s[l][r / NF][r % NF] = W1[t];
    }
    __syncthreads();

    // ---- gather embeddings (float4) + linear term ----
    const float4* t4 = (const float4*)table;
    for (int t = tid; t < NF * ED4; t += NTHREADS) {
        int k = t / ED4;
        int c = t % ED4;
        emb[k][c] = t4[idx[k] * ED4 + c];
    }
    float partial = 0.0f;
    if (tid < NF) partial = lw[idx[tid]];
    __syncthreads();

    // ---- compute: thread owns (i-block of 4, rank j); 2 tasks per thread ----
    const int iblk = tid & 15;          // 16 i-blocks of 4 -> ED=64
    const int j0   = tid >> 4;          // 16 base ranks

    #pragma unroll
    for (int t2 = 0; t2 < 2; t2++) {
        const int j = j0 + 16 * t2;     // ranks 0..31

        float4 A0 = {0,0,0,0}, A1 = {0,0,0,0};
        float4 B0 = {0,0,0,0}, B1 = {0,0,0,0}, B2 = {0,0,0,0};

        #pragma unroll 13
        for (int k = 0; k < NF; k++) {
            const float4 e  = emb[k][iblk];
            const float  u0 = w0s[0][j][k];
            const float  u1 = w0s[1][j][k];
            const float  v0 = w1s[0][j][k];
            const float  v1 = w1s[1][j][k];
            const float  v2 = w1s[2][j][k];

            A0.x += u0 * e.x; A0.y += u0 * e.y; A0.z += u0 * e.z; A0.w += u0 * e.w;
            A1.x += u1 * e.x; A1.y += u1 * e.y; A1.z += u1 * e.z; A1.w += u1 * e.w;
            B0.x += v0 * e.x; B0.y += v0 * e.y; B0.z += v0 * e.z; B0.w += v0 * e.w;
            B1.x += v1 * e.x; B1.y += v1 * e.y; B1.z += v1 * e.z; B1.w += v1 * e.w;
            B2.x += v2 * e.x; B2.y += v2 * e.y; B2.z += v2 * e.z; B2.w += v2 * e.w;
        }

        partial += A0.x * A1.x + A0.y * A1.y + A0.z * A1.z + A0.w * A1.w;
        partial += B0.x * B1.x * B2.x + B0.y * B1.y * B2.y
                 + B0.z * B1.z * B2.z + B0.w * B1.w * B2.w;
    }

    // ---- block reduction ----
    #pragma unroll
    for (int o = 16; o > 0; o >>= 1)
        partial += __shfl_down_sync(0xffffffffu, partial, o);
    if ((tid & 31) == 0) red[tid >> 5] = partial;
    __syncthreads();
    if (tid == 0) {
        float s = lb[0];
        #pragma unroll
        for (int w = 0; w < NTHREADS / 32; w++) s += red[w];
        out[b] = s;
    }
}

extern "C" void kernel_launch(void* const* d_in, const int* in_sizes, int n_in,
                              void* d_out, int out_size)
{
    const int*   x     = (const int*)  d_in[0];
    const float* table = (const float*)d_in[1];
    const float* lw    = (const float*)d_in[2];
    const float* lb    = (const float*)d_in[3];
    const float* W0    = (const float*)d_in[4];
    const float* W1    = (const float*)d_in[5];
    float*       out   = (float*)d_out;
    (void)in_sizes; (void)n_in; (void)out_size;

    tfm_kernel<<<BATCH, NTHREADS>>>(x, table, lw, lb, W0, W1, out);
}

// round 2
// speedup vs baseline: 1.2476x; 1.2476x over previous
#include <cuda_runtime.h>

#define BATCH 8192
#define NF    39
#define NKP   40          // k padded to 40 (even, covers 4-blocks)
#define ED    64
#define RANK  32
#define NTH   256

typedef unsigned long long ull;

__device__ __forceinline__ ull fdup(float x) {
    ull d; asm("mov.b64 %0, {%1, %1};" : "=l"(d) : "f"(x)); return d;
}
__device__ __forceinline__ void fma2(ull& d, ull a, ull b) {
    asm("fma.rn.f32x2 %0, %1, %2, %0;" : "+l"(d) : "l"(a), "l"(b));
}
__device__ __forceinline__ float lo32(ull u) { return __uint_as_float((unsigned)u); }
__device__ __forceinline__ float hi32(ull u) { return __uint_as_float((unsigned)(u >> 32)); }

__global__ __launch_bounds__(NTH, 3)
void tfm_kernel(const int*   __restrict__ x,
                const float* __restrict__ table,
                const float* __restrict__ lw,
                const float* __restrict__ lb,
                const float* __restrict__ W0,
                const float* __restrict__ W1,
                float*       __restrict__ out)
{
    __shared__ float4 emb[NKP][ED / 4];                 // 10240 B, row 39 zeroed
    __shared__ __align__(16) float2 wp[5][16][NKP];     // 25600 B, paired (j, j+16)
    __shared__ int   idx[NF];
    __shared__ float red[NTH / 32];

    const int b   = blockIdx.x;
    const int tid = threadIdx.x;

    if (tid < NF) idx[tid] = x[b * NF + tid];

    // ---- stage W pre-paired along (j, j+16); zero-pad k=39 ----
    for (int t = tid; t < 5 * 16 * NKP; t += NTH) {
        int s = t / (16 * NKP);
        int r = t - s * (16 * NKP);
        int j = r / NKP;
        int k = r - j * NKP;
        float lo = 0.f, hi = 0.f;
        if (k < NF) {
            const float* Ws = (s < 2) ? (W0 + s * RANK * NF)
                                      : (W1 + (s - 2) * RANK * NF);
            lo = Ws[j * NF + k];
            hi = Ws[(j + 16) * NF + k];
        }
        wp[s][j][k] = make_float2(lo, hi);
    }
    __syncthreads();   // idx ready for gather

    // ---- gather embeddings (float4) + linear term ----
    const float4* t4 = (const float4*)table;
    for (int t = tid; t < NF * 16; t += NTH) {
        int k = t >> 4, c = t & 15;
        emb[k][c] = t4[idx[k] * 16 + c];
    }
    if (tid < 16) emb[NF][tid] = make_float4(0.f, 0.f, 0.f, 0.f);
    float partial = (tid < NF) ? lw[idx[tid]] : 0.f;
    __syncthreads();

    // ---- compute ----
    // thread owns: 4 embed dims (ig) x rank-pair (jj, jj+16 via f32x2 lanes)
    const int ig = tid & 15;
    const int jj = tid >> 4;

    ull acc[5][4];
    #pragma unroll
    for (int s = 0; s < 5; s++)
        #pragma unroll
        for (int i = 0; i < 4; i++) acc[s][i] = 0ull;

    #pragma unroll
    for (int k2 = 0; k2 < NKP / 2; k2++) {
        const int k0 = 2 * k2;
        const float4 ea = emb[k0][ig];
        const float4 eb = emb[k0 + 1][ig];
        const ull a0 = fdup(ea.x), a1 = fdup(ea.y), a2 = fdup(ea.z), a3 = fdup(ea.w);
        const ull b0 = fdup(eb.x), b1 = fdup(eb.y), b2 = fdup(eb.z), b3 = fdup(eb.w);

        #pragma unroll
        for (int s = 0; s < 5; s++) {
            const ulonglong2 w2 = *(const ulonglong2*)&wp[s][jj][k0];  // {k0, k0+1} pairs
            fma2(acc[s][0], a0, w2.x); fma2(acc[s][1], a1, w2.x);
            fma2(acc[s][2], a2, w2.x); fma2(acc[s][3], a3, w2.x);
            fma2(acc[s][0], b0, w2.y); fma2(acc[s][1], b1, w2.y);
            fma2(acc[s][2], b2, w2.y); fma2(acc[s][3], b3, w2.y);
        }
    }

    // ---- per-thread epilogue: products over l, both rank-lanes ----
    #pragma unroll
    for (int i = 0; i < 4; i++) {
        partial += lo32(acc[0][i]) * lo32(acc[1][i])
                 + hi32(acc[0][i]) * hi32(acc[1][i]);
        partial += lo32(acc[2][i]) * lo32(acc[3][i]) * lo32(acc[4][i])
                 + hi32(acc[2][i]) * hi32(acc[3][i]) * hi32(acc[4][i]);
    }

    // ---- block reduction ----
    #pragma unroll
    for (int o = 16; o > 0; o >>= 1)
        partial += __shfl_down_sync(0xffffffffu, partial, o);
    if ((tid & 31) == 0) red[tid >> 5] = partial;
    __syncthreads();
    if (tid == 0) {
        float s = lb[0];
        #pragma unroll
        for (int w = 0; w < NTH / 32; w++) s += red[w];
        out[b] = s;
    }
}

extern "C" void kernel_launch(void* const* d_in, const int* in_sizes, int n_in,
                              void* d_out, int out_size)
{
    const int*   x     = (const int*)  d_in[0];
    const float* table = (const float*)d_in[1];
    const float* lw    = (const float*)d_in[2];
    const float* lb    = (const float*)d_in[3];
    const float* W0    = (const float*)d_in[4];
    const float* W1    = (const float*)d_in[5];
    float*       out   = (float*)d_out;
    (void)in_sizes; (void)n_in; (void)out_size;

    tfm_kernel<<<BATCH, NTH>>>(x, table, lw, lb, W0, W1, out);
}

// round 4
// speedup vs baseline: 1.5467x; 1.2398x over previous
#include <cuda_runtime.h>
#include <cuda_bf16.h>
#include <cstdint>

#define NF     39
#define BATCH  8192
#define NTH    256
#define TPC    2
#define NCTA   (BATCH / 2 / TPC)     // 2048

// smem map (dynamic)
#define SM_IDX   16                  // int[78]
#define SM_LIN   336                 // float[78]
#define SM_RED   656                 // float[8]
#define SM_A     1024                // 128 rows x 272 B (K=128 bf16 + 8 pad)
#define SA       272
#define SM_B     (1024 + 128*SA)     // 160 rows x 272 B
#define SMEM_TOTAL (1024 + 128*SA + 160*SA)   // 79360

static __device__ __forceinline__ uint32_t s2u(const void* p){
    uint32_t a;
    asm("{ .reg .u64 t; cvta.to.shared.u64 t, %1; cvt.u32.u64 %0, t; }" : "=r"(a) : "l"(p));
    return a;
}

#define LDSM4(r, a) \
    asm volatile("ldmatrix.sync.aligned.m8n8.x4.shared.b16 {%0,%1,%2,%3}, [%4];" \
        : "=r"((r)[0]),"=r"((r)[1]),"=r"((r)[2]),"=r"((r)[3]) : "r"(a))
#define LDSM2(r, a) \
    asm volatile("ldmatrix.sync.aligned.m8n8.x2.shared.b16 {%0,%1}, [%2];" \
        : "=r"((r)[0]),"=r"((r)[1]) : "r"(a))
#define MMA16816(d, a, b) \
    asm volatile("mma.sync.aligned.m16n8k16.row.col.f32.bf16.bf16.f32 " \
        "{%0,%1,%2,%3},{%4,%5,%6,%7},{%8,%9},{%0,%1,%2,%3};" \
        : "+f"((d)[0]),"+f"((d)[1]),"+f"((d)[2]),"+f"((d)[3]) \
        : "r"((a)[0]),"r"((a)[1]),"r"((a)[2]),"r"((a)[3]), "r"((b)[0]),"r"((b)[1]))

static __device__ __forceinline__ void split1(float v, uint16_t& h, uint16_t& l){
    __nv_bfloat16 hb = __float2bfloat16_rn(v);
    __nv_bfloat16 lb = __float2bfloat16_rn(v - __bfloat162float(hb));
    h = __bfloat16_as_ushort(hb);
    l = __bfloat16_as_ushort(lb);
}

__global__ __launch_bounds__(NTH, 2)
void tfm_mma_kernel(const int*   __restrict__ x,
                    const float* __restrict__ table,
                    const float* __restrict__ lw,
                    const float* __restrict__ lb,
                    const float* __restrict__ W0,
                    const float* __restrict__ W1,
                    float*       __restrict__ out)
{
    extern __shared__ char sm[];
    const uint32_t su  = s2u(sm);
    const int tid = threadIdx.x;
    const int wid = tid >> 5;
    const int lid = tid & 31;

    int*   idxs = (int*)(sm + SM_IDX);
    float* linb = (float*)(sm + SM_LIN);
    float* redb = (float*)(sm + SM_RED);

    // ---- zero A+B regions once (covers K-tail pads) ----
    for (int t = tid; t < (SMEM_TOTAL - 1024) / 16; t += NTH)
        ((float4*)(sm + 1024))[t] = make_float4(0.f, 0.f, 0.f, 0.f);
    __syncthreads();

    // ---- build B once: rows n = s*32+j; K layout [Whi|Whi|Wlo|0] ----
    for (int t = tid; t < 160 * NF; t += NTH) {
        int n = t / NF, k = t - n * NF;
        int s = n >> 5, j = n & 31;
        float w = (s < 2) ? W0[(s * 32 + j) * NF + k]
                          : W1[((s - 2) * 32 + j) * NF + k];
        uint16_t h, l; split1(w, h, l);
        char* rp = sm + SM_B + n * SA;
        *(uint16_t*)(rp + 2*k)          = h;
        *(uint16_t*)(rp + 2*k + 2*NF)   = h;
        *(uint16_t*)(rp + 2*k + 4*NF)   = l;
    }
    __syncthreads();

    // warp tiling: wm = batch row within tile, wj = rank octet
    const int wm = wid & 1;
    const int wj = wid >> 1;
    const uint32_t aBase = su + SM_A + (uint32_t)(wm*64 + (lid & 15)) * SA + (uint32_t)(lid >> 4) * 16u;
    const uint32_t bBase = su + SM_B + (uint32_t)(wj*8  + (lid & 7 )) * SA + (uint32_t)((lid >> 3) & 1) * 16u;

    for (int tt = 0; tt < TPC; tt++) {
        const int b0 = (blockIdx.x * TPC + tt) * 2;

        if (tid < 2 * NF) {
            int xi = x[(b0 + tid / NF) * NF + (tid % NF)];
            idxs[tid] = xi;
            linb[tid] = lw[xi];
        }
        __syncthreads();

        // ---- build A: rows m = b2*64+i; K layout [Ehi|Elo|Ehi|0] ----
        {
            const int m    = tid & 127;
            const int half = tid >> 7;
            const int b2 = m >> 6, i = m & 63;
            const int k0 = half ? 20 : 0;
            const int kn = half ? 19 : 20;
            char* rp = sm + SM_A + m * SA;
            const int* ib = idxs + b2 * NF;
            for (int kk = 0; kk < kn; kk++) {
                int k = k0 + kk;
                float e = __ldg(table + (size_t)ib[k] * 64 + i);
                uint16_t h, l; split1(e, h, l);
                *(uint16_t*)(rp + 2*k)          = h;
                *(uint16_t*)(rp + 2*k + 2*NF)   = l;
                *(uint16_t*)(rp + 2*k + 4*NF)   = h;
            }
        }
        __syncthreads();

        float partial = 0.f;

        // ---- pass 1: segments 0,1 (pair term) ----
        {
            float acc[2][4][4];
            #pragma unroll
            for (int s = 0; s < 2; s++)
                #pragma unroll
                for (int mt = 0; mt < 4; mt++)
                    #pragma unroll
                    for (int e = 0; e < 4; e++) acc[s][mt][e] = 0.f;

            #pragma unroll
            for (int ks = 0; ks < 8; ks++) {
                uint32_t af[4][4];
                #pragma unroll
                for (int mt = 0; mt < 4; mt++)
                    LDSM4(af[mt], aBase + (uint32_t)mt * (16u*SA) + (uint32_t)ks * 32u);
                #pragma unroll
                for (int s = 0; s < 2; s++) {
                    uint32_t bf[2];
                    LDSM2(bf, bBase + (uint32_t)s * (32u*SA) + (uint32_t)ks * 32u);
                    #pragma unroll
                    for (int mt = 0; mt < 4; mt++) MMA16816(acc[s][mt], af[mt], bf);
                }
            }
            #pragma unroll
            for (int mt = 0; mt < 4; mt++)
                #pragma unroll
                for (int e = 0; e < 4; e++)
                    partial += acc[0][mt][e] * acc[1][mt][e];
        }

        // ---- pass 2: segments 2,3,4 (triple term) ----
        {
            float acc[3][4][4];
            #pragma unroll
            for (int s = 0; s < 3; s++)
                #pragma unroll
                for (int mt = 0; mt < 4; mt++)
                    #pragma unroll
                    for (int e = 0; e < 4; e++) acc[s][mt][e] = 0.f;

            #pragma unroll
            for (int ks = 0; ks < 8; ks++) {
                uint32_t af[4][4];
                #pragma unroll
                for (int mt = 0; mt < 4; mt++)
                    LDSM4(af[mt], aBase + (uint32_t)mt * (16u*SA) + (uint32_t)ks * 32u);
                #pragma unroll
                for (int s = 0; s < 3; s++) {
                    uint32_t bf[2];
                    LDSM2(bf, bBase + (uint32_t)(s + 2) * (32u*SA) + (uint32_t)ks * 32u);
                    #pragma unroll
                    for (int mt = 0; mt < 4; mt++) MMA16816(acc[s][mt], af[mt], bf);
                }
            }
            #pragma unroll
            for (int mt = 0; mt < 4; mt++)
                #pragma unroll
                for (int e = 0; e < 4; e++)
                    partial += acc[0][mt][e] * acc[1][mt][e] * acc[2][mt][e];
        }

        // ---- reduce: warp -> red[wid]; wm selects batch row ----
        #pragma unroll
        for (int o = 16; o > 0; o >>= 1)
            partial += __shfl_down_sync(0xffffffffu, partial, o);
        if (lid == 0) redb[wid] = partial;
        __syncthreads();

        if (tid == 0) {
            float l0 = lb[0], l1 = lb[0];
            #pragma unroll
            for (int k = 0; k < NF; k++) { l0 += linb[k]; l1 += linb[NF + k]; }
            out[b0]     = l0 + redb[0] + redb[2] + redb[4] + redb[6];
            out[b0 + 1] = l1 + redb[1] + redb[3] + redb[5] + redb[7];
        }
        __syncthreads();
    }
}

extern "C" void kernel_launch(void* const* d_in, const int* in_sizes, int n_in,
                              void* d_out, int out_size)
{
    const int*   x     = (const int*)  d_in[0];
    const float* table = (const float*)d_in[1];
    const float* lw    = (const float*)d_in[2];
    const float* lb    = (const float*)d_in[3];
    const float* W0    = (const float*)d_in[4];
    const float* W1    = (const float*)d_in[5];
    float*       out   = (float*)d_out;
    (void)in_sizes; (void)n_in; (void)out_size;

    cudaFuncSetAttribute(tfm_mma_kernel, cudaFuncAttributeMaxDynamicSharedMemorySize, SMEM_TOTAL);
    tfm_mma_kernel<<<NCTA, NTH, SMEM_TOTAL>>>(x, table, lw, lb, W0, W1, out);
}

// round 5
// speedup vs baseline: 2.2497x; 1.4545x over previous
#include <cuda_runtime.h>
#include <cuda_bf16.h>
#include <cstdint>

#define NF     39
#define BATCH  8192
#define NTH    256
#define TPC    4
#define NCTA   (BATCH / TPC)            // 2048

#define SA       272
#define SM_IDX   0                       // int[156]
#define SM_LIN   640                     // float[156]
#define SM_LSUM  1280                    // float[4]
#define SM_RED   1296                    // float[8]
#define SM_A     1408                    // 64 rows x 272 B
#define SM_B     (1408 + 64*SA)          // 160 rows x 272 B
#define SMEM_TOTAL (1408 + 64*SA + 160*SA)   // 62336 B -> 3 CTAs/SM

static __device__ __forceinline__ uint32_t s2u(const void* p){
    uint32_t a;
    asm("{ .reg .u64 t; cvta.to.shared.u64 t, %1; cvt.u32.u64 %0, t; }" : "=r"(a) : "l"(p));
    return a;
}

#define LDSM4(r, a) \
    asm volatile("ldmatrix.sync.aligned.m8n8.x4.shared.b16 {%0,%1,%2,%3}, [%4];" \
        : "=r"((r)[0]),"=r"((r)[1]),"=r"((r)[2]),"=r"((r)[3]) : "r"(a))
#define MMA16816(d, a, b0, b1) \
    asm volatile("mma.sync.aligned.m16n8k16.row.col.f32.bf16.bf16.f32 " \
        "{%0,%1,%2,%3},{%4,%5,%6,%7},{%8,%9},{%0,%1,%2,%3};" \
        : "+f"((d)[0]),"+f"((d)[1]),"+f"((d)[2]),"+f"((d)[3]) \
        : "r"((a)[0]),"r"((a)[1]),"r"((a)[2]),"r"((a)[3]), "r"(b0),"r"(b1))

static __device__ __forceinline__ void split1(float v, uint16_t& h, uint16_t& l){
    __nv_bfloat16 hb = __float2bfloat16_rn(v);
    __nv_bfloat16 lb = __float2bfloat16_rn(v - __bfloat162float(hb));
    h = __bfloat16_as_ushort(hb);
    l = __bfloat16_as_ushort(lb);
}

__global__ __launch_bounds__(NTH, 3)
void tfm_mma_kernel(const int*   __restrict__ x,
                    const float* __restrict__ table,
                    const float* __restrict__ lw,
                    const float* __restrict__ lb,
                    const float* __restrict__ W0,
                    const float* __restrict__ W1,
                    float*       __restrict__ out)
{
    extern __shared__ char sm[];
    const uint32_t su  = s2u(sm);
    const int tid = threadIdx.x;
    const int wid = tid >> 5;
    const int lid = tid & 31;

    int*   idxs = (int*)(sm + SM_IDX);
    float* linb = (float*)(sm + SM_LIN);
    float* lsum = (float*)(sm + SM_LSUM);
    float* redb = (float*)(sm + SM_RED);

    // ---- indices + linear gathers for all TPC tiles ----
    if (tid < TPC * NF) {
        int t = tid / NF, kk = tid % NF;
        int xi = x[(blockIdx.x * TPC + t) * NF + kk];
        idxs[tid] = xi;
        linb[tid] = lw[xi];
    }
    // ---- zero A+B (covers K pads) ----
    for (int t = tid; t < (SMEM_TOTAL - SM_A) / 16; t += NTH)
        ((float4*)(sm + SM_A))[t] = make_float4(0.f, 0.f, 0.f, 0.f);
    __syncthreads();

    // ---- build B once: row n = s*32+j; K layout [Whi|Whi|Wlo|0] ----
    for (int t = tid; t < 160 * NF; t += NTH) {
        int n = t / NF, k = t - n * NF;
        int s = n >> 5, j = n & 31;
        float w = (s < 2) ? W0[(s * 32 + j) * NF + k]
                          : W1[((s - 2) * 32 + j) * NF + k];
        uint16_t h, l; split1(w, h, l);
        char* rp = sm + SM_B + n * SA;
        *(uint16_t*)(rp + 2*k)        = h;
        *(uint16_t*)(rp + 2*k + 2*NF) = h;
        *(uint16_t*)(rp + 2*k + 4*NF) = l;
    }

    // A-build thread mapping: row = embed dim i, k-group of ~10
    const int ai = tid & 63;
    const int kg = tid >> 6;
    const int k0 = kg * 10;
    const int kn = (kg == 3) ? 9 : 10;

    // ---- build A tile 0: K layout [Ehi|Elo|Ehi|0] ----
    {
        char* rp = sm + SM_A + ai * SA;
        #pragma unroll
        for (int kk = 0; kk < 10; kk++) {
            if (kk < kn) {
                int k = k0 + kk;
                float e = __ldg(table + (size_t)idxs[k] * 64 + ai);
                uint16_t h, l; split1(e, h, l);
                *(uint16_t*)(rp + 2*k)        = h;
                *(uint16_t*)(rp + 2*k + 2*NF) = l;
                *(uint16_t*)(rp + 2*k + 4*NF) = h;
            }
        }
    }
    if (tid < TPC) {
        float s = 0.f;
        #pragma unroll
        for (int k = 0; k < NF; k++) s += linb[tid * NF + k];
        lsum[tid] = s;
    }
    __syncthreads();

    // warp tiling: wm = m-half (32 embed dims), wj = rank octet
    const int wm = wid & 1;
    const int wj = wid >> 1;
    const uint32_t aBase = su + SM_A + (uint32_t)(wm*32 + (lid & 15)) * SA + (uint32_t)(lid >> 4) * 16u;
    const uint32_t bBase = su + SM_B + (uint32_t)(wj*8  + (lid & 7 )) * SA + (uint32_t)((lid >> 3) & 3) * 16u;

    for (int tt = 0; tt < TPC; tt++) {
        // ---- prefetch next tile's gathers into registers (overlaps MMA) ----
        float pf[10];
        if (tt + 1 < TPC) {
            const int* ib = idxs + (tt + 1) * NF;
            #pragma unroll
            for (int kk = 0; kk < 10; kk++)
                pf[kk] = (kk < kn) ? __ldg(table + (size_t)ib[k0 + kk] * 64 + ai) : 0.f;
        }

        // ---- single-pass MMA over all 5 segments ----
        float acc[5][2][4];
        #pragma unroll
        for (int s = 0; s < 5; s++)
            #pragma unroll
            for (int mt = 0; mt < 2; mt++)
                #pragma unroll
                for (int e = 0; e < 4; e++) acc[s][mt][e] = 0.f;

        #pragma unroll
        for (int ks2 = 0; ks2 < 4; ks2++) {
            uint32_t af[2][2][4];      // [h][mt]
            #pragma unroll
            for (int h = 0; h < 2; h++)
                #pragma unroll
                for (int mt = 0; mt < 2; mt++)
                    LDSM4(af[h][mt], aBase + (uint32_t)mt * (16u*SA) + (uint32_t)(2*ks2 + h) * 32u);
            #pragma unroll
            for (int s = 0; s < 5; s++) {
                uint32_t bf[4];        // 2 k-steps of B
                LDSM4(bf, bBase + (uint32_t)s * (32u*SA) + (uint32_t)ks2 * 64u);
                #pragma unroll
                for (int h = 0; h < 2; h++)
                    #pragma unroll
                    for (int mt = 0; mt < 2; mt++)
                        MMA16816(acc[s][mt], af[h][mt], bf[2*h], bf[2*h + 1]);
            }
        }
        __syncthreads();               // all A reads complete

        // ---- store prefetched A for next tile ----
        if (tt + 1 < TPC) {
            char* rp = sm + SM_A + ai * SA;
            #pragma unroll
            for (int kk = 0; kk < 10; kk++) {
                if (kk < kn) {
                    int k = k0 + kk;
                    uint16_t h, l; split1(pf[kk], h, l);
                    *(uint16_t*)(rp + 2*k)        = h;
                    *(uint16_t*)(rp + 2*k + 2*NF) = l;
                    *(uint16_t*)(rp + 2*k + 4*NF) = h;
                }
            }
        }

        // ---- epilogue: pair + triple, warp reduce ----
        float partial = 0.f;
        #pragma unroll
        for (int mt = 0; mt < 2; mt++)
            #pragma unroll
            for (int e = 0; e < 4; e++)
                partial += acc[0][mt][e] * acc[1][mt][e]
                         + acc[2][mt][e] * acc[3][mt][e] * acc[4][mt][e];

        #pragma unroll
        for (int o = 16; o > 0; o >>= 1)
            partial += __shfl_down_sync(0xffffffffu, partial, o);
        if (lid == 0) redb[wid] = partial;
        __syncthreads();               // redb ready + A writes visible

        if (tid == 0) {
            float s = lb[0] + lsum[tt];
            #pragma unroll
            for (int w = 0; w < 8; w++) s += redb[w];
            out[blockIdx.x * TPC + tt] = s;
        }
    }
}

extern "C" void kernel_launch(void* const* d_in, const int* in_sizes, int n_in,
                              void* d_out, int out_size)
{
    const int*   x     = (const int*)  d_in[0];
    const float* table = (const float*)d_in[1];
    const float* lw    = (const float*)d_in[2];
    const float* lb    = (const float*)d_in[3];
    const float* W0    = (const float*)d_in[4];
    const float* W1    = (const float*)d_in[5];
    float*       out   = (float*)d_out;
    (void)in_sizes; (void)n_in; (void)out_size;

    cudaFuncSetAttribute(tfm_mma_kernel, cudaFuncAttributeMaxDynamicSharedMemorySize, SMEM_TOTAL);
    tfm_mma_kernel<<<NCTA, NTH, SMEM_TOTAL>>>(x, table, lw, lb, W0, W1, out);
}

// round 6
// speedup vs baseline: 4.4558x; 1.9806x over previous
#include <cuda_runtime.h>
#include <cuda_fp16.h>
#include <cstdint>

#define NF     39
#define BATCH  8192
#define NTH    256
#define TPC    8
#define NCTA   (BATCH / TPC)            // 1024

#define SA     112                      // row stride bytes (48 fp16 + 8 pad)
#define SAH    56                       // in halves

static __device__ __forceinline__ uint32_t s2u(const void* p){
    uint32_t a;
    asm("{ .reg .u64 t; cvta.to.shared.u64 t, %1; cvt.u32.u64 %0, t; }" : "=r"(a) : "l"(p));
    return a;
}

#define LDSM4(r, a) \
    asm volatile("ldmatrix.sync.aligned.m8n8.x4.shared.b16 {%0,%1,%2,%3}, [%4];" \
        : "=r"((r)[0]),"=r"((r)[1]),"=r"((r)[2]),"=r"((r)[3]) : "r"(a))
#define LDSM2(r, a) \
    asm volatile("ldmatrix.sync.aligned.m8n8.x2.shared.b16 {%0,%1}, [%2];" \
        : "=r"((r)[0]),"=r"((r)[1]) : "r"(a))
#define MMAF16(d, a, b0, b1) \
    asm volatile("mma.sync.aligned.m16n8k16.row.col.f32.f16.f16.f32 " \
        "{%0,%1,%2,%3},{%4,%5,%6,%7},{%8,%9},{%0,%1,%2,%3};" \
        : "+f"((d)[0]),"+f"((d)[1]),"+f"((d)[2]),"+f"((d)[3]) \
        : "r"((a)[0]),"r"((a)[1]),"r"((a)[2]),"r"((a)[3]), "r"(b0),"r"(b1))

__global__ __launch_bounds__(NTH, 3)
void tfm_mma_kernel(const int*   __restrict__ x,
                    const float* __restrict__ table,
                    const float* __restrict__ lw,
                    const float* __restrict__ lb,
                    const float* __restrict__ W0,
                    const float* __restrict__ W1,
                    float*       __restrict__ out)
{
    __shared__ int   idxs[TPC * NF];
    __shared__ float linb[TPC * NF];
    __shared__ float lsum[TPC];
    __shared__ float redb[8];
    __shared__ __align__(16) uint16_t Abuf[64 * SAH];    // 7168 B
    __shared__ __align__(16) uint16_t Bbuf[160 * SAH];   // 17920 B

    const int tid = threadIdx.x;
    const int wid = tid >> 5;
    const int lid = tid & 31;

    // ---- indices + linear gathers for all tiles ----
    for (int t = tid; t < TPC * NF; t += NTH) {
        int xi = x[(blockIdx.x * TPC + t / NF) * NF + (t % NF)];
        idxs[t] = xi;
        linb[t] = lw[xi];
    }
    // ---- zero A+B (covers K pads) ----
    for (int t = tid; t < 64 * SA / 16; t += NTH)
        ((float4*)Abuf)[t] = make_float4(0.f, 0.f, 0.f, 0.f);
    for (int t = tid; t < 160 * SA / 16; t += NTH)
        ((float4*)Bbuf)[t] = make_float4(0.f, 0.f, 0.f, 0.f);
    __syncthreads();

    // ---- build B once: row n = s*32 + j, fp16 ----
    for (int t = tid; t < 160 * NF; t += NTH) {
        int n = t / NF, k = t - n * NF;
        int s = n >> 5, j = n & 31;
        float w = (s < 2) ? W0[(s * 32 + j) * NF + k]
                          : W1[((s - 2) * 32 + j) * NF + k];
        Bbuf[n * SAH + k] = __half_as_ushort(__float2half_rn(w));
    }

    // A-build mapping: row = embed dim ai, k-group of ~10
    const int ai = tid & 63;
    const int kg = tid >> 6;
    const int k0 = kg * 10;
    const int kn = (kg == 3) ? 9 : 10;

    // ---- build A tile 0 ----
    #pragma unroll
    for (int kk = 0; kk < 10; kk++) {
        if (kk < kn) {
            float e = __ldg(table + (size_t)idxs[k0 + kk] * 64 + ai);
            Abuf[ai * SAH + k0 + kk] = __half_as_ushort(__float2half_rn(e));
        }
    }
    if (tid < TPC) {
        float s = 0.f;
        #pragma unroll
        for (int k = 0; k < NF; k++) s += linb[tid * NF + k];
        lsum[tid] = s;
    }
    __syncthreads();

    // warp tiling: wm = m-half (32 embed dims), wj = rank octet
    const int wm = wid & 1;
    const int wj = wid >> 1;
    const uint32_t aBase = s2u(Abuf) + (uint32_t)(wm*32 + (lid & 15)) * SA + (uint32_t)(lid >> 4) * 16u;
    const uint32_t bBase = s2u(Bbuf) + (uint32_t)(wj*8  + (lid & 7 )) * SA + (uint32_t)((lid >> 3) & 1) * 16u;

    for (int tt = 0; tt < TPC; tt++) {
        // ---- prefetch next tile's gathers (overlaps MMA) ----
        float pf[10];
        if (tt + 1 < TPC) {
            const int* ib = idxs + (tt + 1) * NF;
            #pragma unroll
            for (int kk = 0; kk < 10; kk++)
                pf[kk] = (kk < kn) ? __ldg(table + (size_t)ib[k0 + kk] * 64 + ai) : 0.f;
        }

        // ---- single-pass MMA: 5 segments x 2 m-tiles x 3 k-steps ----
        float acc[5][2][4];
        #pragma unroll
        for (int s = 0; s < 5; s++)
            #pragma unroll
            for (int mt = 0; mt < 2; mt++)
                #pragma unroll
                for (int e = 0; e < 4; e++) acc[s][mt][e] = 0.f;

        #pragma unroll
        for (int ks = 0; ks < 3; ks++) {
            uint32_t af0[4], af1[4];
            LDSM4(af0, aBase + (uint32_t)ks * 32u);
            LDSM4(af1, aBase + 16u*SA + (uint32_t)ks * 32u);
            #pragma unroll
            for (int s = 0; s < 5; s++) {
                uint32_t bf[2];
                LDSM2(bf, bBase + (uint32_t)s * (32u*SA) + (uint32_t)ks * 32u);
                MMAF16(acc[s][0], af0, bf[0], bf[1]);
                MMAF16(acc[s][1], af1, bf[0], bf[1]);
            }
        }
        __syncthreads();               // all A reads complete

        // ---- store prefetched A for next tile ----
        if (tt + 1 < TPC) {
            #pragma unroll
            for (int kk = 0; kk < 10; kk++)
                if (kk < kn)
                    Abuf[ai * SAH + k0 + kk] = __half_as_ushort(__float2half_rn(pf[kk]));
        }

        // ---- epilogue: pair + triple, warp reduce ----
        float partial = 0.f;
        #pragma unroll
        for (int mt = 0; mt < 2; mt++)
            #pragma unroll
            for (int e = 0; e < 4; e++)
                partial += acc[0][mt][e] * acc[1][mt][e]
                         + acc[2][mt][e] * acc[3][mt][e] * acc[4][mt][e];

        #pragma unroll
        for (int o = 16; o > 0; o >>= 1)
            partial += __shfl_down_sync(0xffffffffu, partial, o);
        if (lid == 0) redb[wid] = partial;
        __syncthreads();

        if (tid == 0) {
            float s = lb[0] + lsum[tt];
            #pragma unroll
            for (int w = 0; w < 8; w++) s += redb[w];
            out[blockIdx.x * TPC + tt] = s;
        }
    }
}

extern "C" void kernel_launch(void* const* d_in, const int* in_sizes, int n_in,
                              void* d_out, int out_size)
{
    const int*   x     = (const int*)  d_in[0];
    const float* table = (const float*)d_in[1];
    const float* lw    = (const float*)d_in[2];
    const float* lb    = (const float*)d_in[3];
    const float* W0    = (const float*)d_in[4];
    const float* W1    = (const float*)d_in[5];
    float*       out   = (float*)d_out;
    (void)in_sizes; (void)n_in; (void)out_size;

    tfm_mma_kernel<<<NCTA, NTH>>>(x, table, lw, lb, W0, W1, out);
}

// round 8
// speedup vs baseline: 5.1366x; 1.1528x over previous
#include <cuda_runtime.h>
#include <cuda_fp16.h>
#include <cstdint>

#define NF     39
#define BATCH  8192
#define NTH    256
#define TPC    8
#define NCTA   (BATCH / TPC)            // 1024

#define SA     112                      // A/B row stride bytes (48 fp16 + pad)
#define SAH    56

static __device__ __forceinline__ uint32_t s2u(const void* p){
    uint32_t a;
    asm("{ .reg .u64 t; cvta.to.shared.u64 t, %1; cvt.u32.u64 %0, t; }" : "=r"(a) : "l"(p));
    return a;
}

#define LDSM4(r, a) \
    asm volatile("ldmatrix.sync.aligned.m8n8.x4.shared.b16 {%0,%1,%2,%3}, [%4];" \
        : "=r"((r)[0]),"=r"((r)[1]),"=r"((r)[2]),"=r"((r)[3]) : "r"(a))
#define LDSM2(r, a) \
    asm volatile("ldmatrix.sync.aligned.m8n8.x2.shared.b16 {%0,%1}, [%2];" \
        : "=r"((r)[0]),"=r"((r)[1]) : "r"(a))
// f16 accumulate: D/C are 2x b32 (4 halves)
#define MMAH(d, a, b0, b1) \
    asm volatile("mma.sync.aligned.m16n8k16.row.col.f16.f16.f16.f16 " \
        "{%0,%1},{%2,%3,%4,%5},{%6,%7},{%0,%1};" \
        : "+r"((d)[0]),"+r"((d)[1]) \
        : "r"((a)[0]),"r"((a)[1]),"r"((a)[2]),"r"((a)[3]), "r"(b0),"r"(b1))

__global__ __launch_bounds__(NTH, 4)
void tfm_mma_kernel(const int*   __restrict__ x,
                    const float* __restrict__ table,
                    const float* __restrict__ lw,
                    const float* __restrict__ lb,
                    const float* __restrict__ W0,
                    const float* __restrict__ W1,
                    float*       __restrict__ out)
{
    __shared__ int   idxs[TPC * NF];
    __shared__ float linb[TPC * NF];
    __shared__ float lsum[TPC];
    __shared__ float redb[TPC][8];
    __shared__ __align__(16) uint16_t Abuf[2][64 * SAH]; // 2 x 7168 B
    __shared__ __align__(16) uint16_t Bbuf[160 * SAH];   // 17920 B

    const int tid = threadIdx.x;
    const int wid = tid >> 5;
    const int lid = tid & 31;

    // ---- indices + linear gathers for all tiles ----
    for (int t = tid; t < TPC * NF; t += NTH) {
        int xi = x[(blockIdx.x * TPC + t / NF) * NF + (t % NF)];
        idxs[t] = xi;
        linb[t] = lw[xi];
    }
    // ---- zero A buffers + B (covers K pads) ----
    for (int t = tid; t < 2 * 64 * SA / 16; t += NTH)
        ((float4*)Abuf)[t] = make_float4(0.f, 0.f, 0.f, 0.f);
    for (int t = tid; t < 160 * SA / 16; t += NTH)
        ((float4*)Bbuf)[t] = make_float4(0.f, 0.f, 0.f, 0.f);
    __syncthreads();

    // ---- build B once: row n = s*32 + j, fp16 ----
    for (int t = tid; t < 160 * NF; t += NTH) {
        int n = t / NF, k = t - n * NF;
        int s = n >> 5, j = n & 31;
        float w = (s < 2) ? W0[(s * 32 + j) * NF + k]
                          : W1[((s - 2) * 32 + j) * NF + k];
        Bbuf[n * SAH + k] = __half_as_ushort(__float2half_rn(w));
    }

    // A-build mapping: row = embed dim ai, k-group of 10 (pads write 0)
    const int ai = tid & 63;
    const int kg = tid >> 6;
    const int k0 = kg * 10;
    const int kn = (kg == 3) ? 9 : 10;

    // ---- build A tile 0 into buffer 0 (packed u32 stores) ----
    {
        uint32_t pk[5];
        #pragma unroll
        for (int p = 0; p < 5; p++) {
            int ka = k0 + 2*p, kb = ka + 1;
            float ea = (2*p     < kn) ? __ldg(table + (size_t)idxs[ka] * 64 + ai) : 0.f;
            float eb = (2*p + 1 < kn) ? __ldg(table + (size_t)idxs[kb] * 64 + ai) : 0.f;
            pk[p] = (uint32_t)__half_as_ushort(__float2half_rn(ea))
                  | ((uint32_t)__half_as_ushort(__float2half_rn(eb)) << 16);
        }
        uint32_t* ap = (uint32_t*)&Abuf[0][ai * SAH + k0];
        #pragma unroll
        for (int p = 0; p < 5; p++) ap[p] = pk[p];
    }
    if (tid < TPC) {
        float s = 0.f;
        #pragma unroll
        for (int k = 0; k < NF; k++) s += linb[tid * NF + k];
        lsum[tid] = s;
    }
    __syncthreads();

    // warp tiling: wm = m-half (32 embed dims), wj = rank octet
    const int wm = wid & 1;
    const int wj = wid >> 1;
    const uint32_t aOff  = (uint32_t)(wm*32 + (lid & 15)) * SA + (uint32_t)(lid >> 4) * 16u;
    const uint32_t aB0   = s2u(Abuf[0]) + aOff;
    const uint32_t aB1   = s2u(Abuf[1]) + aOff;
    const uint32_t bBase = s2u(Bbuf) + (uint32_t)(wj*8 + (lid & 7)) * SA + (uint32_t)((lid >> 3) & 1) * 16u;

    for (int tt = 0; tt < TPC; tt++) {
        const uint32_t aBase = (tt & 1) ? aB1 : aB0;

        // ---- prefetch next tile's gathers -> packed halves (overlaps MMA) ----
        uint32_t pk[5];
        if (tt + 1 < TPC) {
            const int* ib = idxs + (tt + 1) * NF;
            #pragma unroll
            for (int p = 0; p < 5; p++) {
                int ka = k0 + 2*p, kb = ka + 1;
                float ea = (2*p     < kn) ? __ldg(table + (size_t)ib[ka] * 64 + ai) : 0.f;
                float eb = (2*p + 1 < kn) ? __ldg(table + (size_t)ib[kb] * 64 + ai) : 0.f;
                pk[p] = (uint32_t)__half_as_ushort(__float2half_rn(ea))
                      | ((uint32_t)__half_as_ushort(__float2half_rn(eb)) << 16);
            }
        }

        // ---- single-pass MMA: 5 segments x 2 m-tiles x 3 k-steps, f16 acc ----
        uint32_t acc[5][2][2];
        #pragma unroll
        for (int s = 0; s < 5; s++)
            #pragma unroll
            for (int mt = 0; mt < 2; mt++)
                acc[s][mt][0] = acc[s][mt][1] = 0u;

        #pragma unroll
        for (int ks = 0; ks < 3; ks++) {
            uint32_t af0[4], af1[4];
            LDSM4(af0, aBase + (uint32_t)ks * 32u);
            LDSM4(af1, aBase + 16u*SA + (uint32_t)ks * 32u);
            #pragma unroll
            for (int s = 0; s < 5; s++) {
                uint32_t bf[2];
                LDSM2(bf, bBase + (uint32_t)s * (32u*SA) + (uint32_t)ks * 32u);
                MMAH(acc[s][0], af0, bf[0], bf[1]);
                MMAH(acc[s][1], af1, bf[0], bf[1]);
            }
        }

        // ---- store prefetched A into the other buffer (no barrier needed) ----
        if (tt + 1 < TPC) {
            uint32_t* ap = (uint32_t*)&Abuf[(tt + 1) & 1][ai * SAH + k0];
            #pragma unroll
            for (int p = 0; p < 5; p++) ap[p] = pk[p];
        }

        // ---- epilogue: pair + triple in fp32, warp reduce, no sync ----
        float partial = 0.f;
        #pragma unroll
        for (int mt = 0; mt < 2; mt++)
            #pragma unroll
            for (int r = 0; r < 2; r++) {
                float2 d0 = __half22float2(*(const __half2*)&acc[0][mt][r]);
                float2 d1 = __half22float2(*(const __half2*)&acc[1][mt][r]);
                float2 d2 = __half22float2(*(const __half2*)&acc[2][mt][r]);
                float2 d3 = __half22float2(*(const __half2*)&acc[3][mt][r]);
                float2 d4 = __half22float2(*(const __half2*)&acc[4][mt][r]);
                partial += d0.x * d1.x + d2.x * d3.x * d4.x;
                partial += d0.y * d1.y + d2.y * d3.y * d4.y;
            }
        #pragma unroll
        for (int o = 16; o > 0; o >>= 1)
            partial += __shfl_down_sync(0xffffffffu, partial, o);
        if (lid == 0) redb[tt][wid] = partial;

        __syncthreads();   // one barrier: A[alt] visible + redb ordering
    }

    // ---- final outputs: 8 threads, 8 tiles ----
    if (tid < TPC) {
        float s = lb[0] + lsum[tid];
        #pragma unroll
        for (int w = 0; w < 8; w++) s += redb[tid][w];
        out[blockIdx.x * TPC + tid] = s;
    }
}

extern "C" void kernel_launch(void* const* d_in, const int* in_sizes, int n_in,
                              void* d_out, int out_size)
{
    const int*   x     = (const int*)  d_in[0];
    const float* table = (const float*)d_in[1];
    const float* lw    = (const float*)d_in[2];
    const float* lb    = (const float*)d_in[3];
    const float* W0    = (const float*)d_in[4];
    const float* W1    = (const float*)d_in[5];
    float*       out   = (float*)d_out;
    (void)in_sizes; (void)n_in; (void)out_size;

    tfm_mma_kernel<<<NCTA, NTH>>>(x, table, lw, lb, W0, W1, out);
}

// round 9
// speedup vs baseline: 5.1525x; 1.0031x over previous
#include <cuda_runtime.h>
#include <cuda_fp16.h>
#include <cstdint>

#define NF     39
#define BATCH  8192
#define NTH    256
#define GRID   592                      // 148 SMs x 4 CTAs = one full wave
#define MAXT   14                       // ceil(8192/592)

#define SA     112                      // A/B row stride bytes (48 fp16 + pad)
#define SAH    56

static __device__ __forceinline__ uint32_t s2u(const void* p){
    uint32_t a;
    asm("{ .reg .u64 t; cvta.to.shared.u64 t, %1; cvt.u32.u64 %0, t; }" : "=r"(a) : "l"(p));
    return a;
}

#define LDSM4(r, a) \
    asm volatile("ldmatrix.sync.aligned.m8n8.x4.shared.b16 {%0,%1,%2,%3}, [%4];" \
        : "=r"((r)[0]),"=r"((r)[1]),"=r"((r)[2]),"=r"((r)[3]) : "r"(a))
#define LDSM2(r, a) \
    asm volatile("ldmatrix.sync.aligned.m8n8.x2.shared.b16 {%0,%1}, [%2];" \
        : "=r"((r)[0]),"=r"((r)[1]) : "r"(a))
#define MMAH(d, a, b0, b1) \
    asm volatile("mma.sync.aligned.m16n8k16.row.col.f16.f16.f16.f16 " \
        "{%0,%1},{%2,%3,%4,%5},{%6,%7},{%0,%1};" \
        : "+r"((d)[0]),"+r"((d)[1]) \
        : "r"((a)[0]),"r"((a)[1]),"r"((a)[2]),"r"((a)[3]), "r"(b0),"r"(b1))

__global__ __launch_bounds__(NTH, 4)
void tfm_mma_kernel(const int*   __restrict__ x,
                    const float* __restrict__ table,
                    const float* __restrict__ lw,
                    const float* __restrict__ lb,
                    const float* __restrict__ W0,
                    const float* __restrict__ W1,
                    float*       __restrict__ out)
{
    __shared__ int   idxr[2][NF];                        // idx ring, 2 tiles ahead
    __shared__ float linA[MAXT][NF];                     // staged lw values per tile
    __shared__ float redb[MAXT][8];                      // per-tile per-warp partials
    __shared__ __align__(16) uint16_t Abuf[2][64 * SAH]; // 2 x 7168 B
    __shared__ __align__(16) uint16_t Bbuf[160 * SAH];   // 17920 B

    const int tid = threadIdx.x;
    const int wid = tid >> 5;
    const int lid = tid & 31;
    const int bid = blockIdx.x;
    const int nt  = (BATCH - bid + GRID - 1) / GRID;     // 13 or 14 tiles

    // ---- zero A buffers + B (covers K pads) ----
    for (int t = tid; t < 2 * 64 * SA / 16; t += NTH)
        ((float4*)Abuf)[t] = make_float4(0.f, 0.f, 0.f, 0.f);
    for (int t = tid; t < 160 * SA / 16; t += NTH)
        ((float4*)Bbuf)[t] = make_float4(0.f, 0.f, 0.f, 0.f);

    // ---- stage tile 0 indices + lin ----
    if (tid < NF) {
        int xi = x[bid * NF + tid];
        idxr[0][tid] = xi;
        linA[0][tid] = lw[xi];
    }
    __syncthreads();

    // ---- build B once: row n = s*32 + j, fp16 ----
    for (int t = tid; t < 160 * NF; t += NTH) {
        int n = t / NF, k = t - n * NF;
        int s = n >> 5, j = n & 31;
        float w = (s < 2) ? W0[(s * 32 + j) * NF + k]
                          : W1[((s - 2) * 32 + j) * NF + k];
        Bbuf[n * SAH + k] = __half_as_ushort(__float2half_rn(w));
    }

    // A-build mapping: row = embed dim ai, k-group of 10
    const int ai = tid & 63;
    const int kg = tid >> 6;
    const int k0 = kg * 10;
    const int kn = (kg == 3) ? 9 : 10;

    // ---- build A tile 0 into buffer 0 ----
    {
        uint32_t pk[5];
        #pragma unroll
        for (int p = 0; p < 5; p++) {
            int ka = k0 + 2*p, kb = ka + 1;
            float ea = (2*p     < kn) ? __ldg(table + (size_t)idxr[0][ka] * 64 + ai) : 0.f;
            float eb = (2*p + 1 < kn) ? __ldg(table + (size_t)idxr[0][kb] * 64 + ai) : 0.f;
            pk[p] = (uint32_t)__half_as_ushort(__float2half_rn(ea))
                  | ((uint32_t)__half_as_ushort(__float2half_rn(eb)) << 16);
        }
        uint32_t* ap = (uint32_t*)&Abuf[0][ai * SAH + k0];
        #pragma unroll
        for (int p = 0; p < 5; p++) ap[p] = pk[p];
    }
    // ---- stage tile 1 ----
    if (nt > 1 && tid < NF) {
        int xi = x[(bid + GRID) * NF + tid];
        idxr[1][tid] = xi;
        linA[1][tid] = lw[xi];
    }
    __syncthreads();

    // warp tiling: wm = m-half (32 embed dims), wj = rank octet
    const int wm = wid & 1;
    const int wj = wid >> 1;
    const uint32_t aOff  = (uint32_t)(wm*32 + (lid & 15)) * SA + (uint32_t)(lid >> 4) * 16u;
    const uint32_t aB0   = s2u(Abuf[0]) + aOff;
    const uint32_t aB1   = s2u(Abuf[1]) + aOff;
    const uint32_t bBase = s2u(Bbuf) + (uint32_t)(wj*8 + (lid & 7)) * SA + (uint32_t)((lid >> 3) & 1) * 16u;

    for (int i = 0; i < nt; i++) {
        const uint32_t aBase = (i & 1) ? aB1 : aB0;

        // ---- prefetch gathers for tile i+1 (overlaps MMA) ----
        uint32_t pk[5];
        if (i + 1 < nt) {
            const int* ib = idxr[(i + 1) & 1];
            #pragma unroll
            for (int p = 0; p < 5; p++) {
                int ka = k0 + 2*p, kb = ka + 1;
                float ea = (2*p     < kn) ? __ldg(table + (size_t)ib[ka] * 64 + ai) : 0.f;
                float eb = (2*p + 1 < kn) ? __ldg(table + (size_t)ib[kb] * 64 + ai) : 0.f;
                pk[p] = (uint32_t)__half_as_ushort(__float2half_rn(ea))
                      | ((uint32_t)__half_as_ushort(__float2half_rn(eb)) << 16);
            }
        }

        // ---- single-pass MMA: 5 segments x 2 m-tiles x 3 k-steps, f16 acc ----
        uint32_t acc[5][2][2];
        #pragma unroll
        for (int s = 0; s < 5; s++)
            #pragma unroll
            for (int mt = 0; mt < 2; mt++)
                acc[s][mt][0] = acc[s][mt][1] = 0u;

        #pragma unroll
        for (int ks = 0; ks < 3; ks++) {
            uint32_t af0[4], af1[4];
            LDSM4(af0, aBase + (uint32_t)ks * 32u);
            LDSM4(af1, aBase + 16u*SA + (uint32_t)ks * 32u);
            #pragma unroll
            for (int s = 0; s < 5; s++) {
                uint32_t bf[2];
                LDSM2(bf, bBase + (uint32_t)s * (32u*SA) + (uint32_t)ks * 32u);
                MMAH(acc[s][0], af0, bf[0], bf[1]);
                MMAH(acc[s][1], af1, bf[0], bf[1]);
            }
        }

        // ---- stage tile i+2 indices + lin (slot (i+2)&1 == i&1, now free) ----
        if (i + 2 < nt && tid < NF) {
            int xi = x[(bid + (i + 2) * GRID) * NF + tid];
            idxr[i & 1][tid] = xi;
            linA[i + 2][tid] = lw[xi];
        }

        // ---- store prefetched A into the other buffer ----
        if (i + 1 < nt) {
            uint32_t* ap = (uint32_t*)&Abuf[(i + 1) & 1][ai * SAH + k0];
            #pragma unroll
            for (int p = 0; p < 5; p++) ap[p] = pk[p];
        }

        // ---- epilogue: pair + triple in fp32, warp reduce ----
        float partial = 0.f;
        #pragma unroll
        for (int mt = 0; mt < 2; mt++)
            #pragma unroll
            for (int r = 0; r < 2; r++) {
                float2 d0 = __half22float2(*(const __half2*)&acc[0][mt][r]);
                float2 d1 = __half22float2(*(const __half2*)&acc[1][mt][r]);
                float2 d2 = __half22float2(*(const __half2*)&acc[2][mt][r]);
                float2 d3 = __half22float2(*(const __half2*)&acc[3][mt][r]);
                float2 d4 = __half22float2(*(const __half2*)&acc[4][mt][r]);
                partial += d0.x * d1.x + d2.x * d3.x * d4.x;
                partial += d0.y * d1.y + d2.y * d3.y * d4.y;
            }
        #pragma unroll
        for (int o = 16; o > 0; o >>= 1)
            partial += __shfl_down_sync(0xffffffffu, partial, o);
        if (lid == 0) redb[i][wid] = partial;

        __syncthreads();   // A[alt] + idxr + redb visible
    }

    // ---- final: each warp finishes ~2 tiles (cross partials + lin + bias) ----
    for (int i = wid; i < nt; i += 8) {
        float s = (lid < 8) ? redb[i][lid] : 0.f;
        s += linA[i][lid];                       // lid 0..31 < 39
        if (lid < NF - 32) s += linA[i][32 + lid];
        #pragma unroll
        for (int o = 16; o > 0; o >>= 1)
            s += __shfl_down_sync(0xffffffffu, s, o);
        if (lid == 0) out[bid + i * GRID] = s + lb[0];
    }
}

extern "C" void kernel_launch(void* const* d_in, const int* in_sizes, int n_in,
                              void* d_out, int out_size)
{
    const int*   x     = (const int*)  d_in[0];
    const float* table = (const float*)d_in[1];
    const float* lw    = (const float*)d_in[2];
    const float* lb    = (const float*)d_in[3];
    const float* W0    = (const float*)d_in[4];
    const float* W1    = (const float*)d_in[5];
    float*       out   = (float*)d_out;
    (void)in_sizes; (void)n_in; (void)out_size;

    tfm_mma_kernel<<<GRID, NTH>>>(x, table, lw, lb, W0, W1, out);
}

// round 10
// speedup vs baseline: 5.6463x; 1.0958x over previous
#include <cuda_runtime.h>
#include <cuda_fp16.h>
#include <cstdint>

#define NF     39
#define BATCH  8192
#define PAIRS  4096
#define NTH    256
#define GRID   444                      // 148 SMs x 3 CTAs = one full wave
#define MAXP   10                       // max pairs per CTA

#define SA     112                      // row stride bytes (48 fp16 + pad)
#define SAH    56

// dynamic smem offsets (bytes)
#define O_IDX  0                        // int [2][80]
#define O_LIN  640                      // float [MAXP][80]
#define O_PB   3840                     // float [MAXP][8][32]
#define O_A    14080                    // u16 [2][128*SAH]  (2 x 14336 B)
#define O_B    42752                    // u16 [160*SAH]     (17920 B)
#define SMEM_TOTAL 60672

static __device__ __forceinline__ uint32_t s2u(const void* p){
    uint32_t a;
    asm("{ .reg .u64 t; cvta.to.shared.u64 t, %1; cvt.u32.u64 %0, t; }" : "=r"(a) : "l"(p));
    return a;
}

#define LDSM4(r, a) \
    asm volatile("ldmatrix.sync.aligned.m8n8.x4.shared.b16 {%0,%1,%2,%3}, [%4];" \
        : "=r"((r)[0]),"=r"((r)[1]),"=r"((r)[2]),"=r"((r)[3]) : "r"(a))
#define LDSM2(r, a) \
    asm volatile("ldmatrix.sync.aligned.m8n8.x2.shared.b16 {%0,%1}, [%2];" \
        : "=r"((r)[0]),"=r"((r)[1]) : "r"(a))
#define MMAH(d, a, b0, b1) \
    asm volatile("mma.sync.aligned.m16n8k16.row.col.f16.f16.f16.f16 " \
        "{%0,%1},{%2,%3,%4,%5},{%6,%7},{%0,%1};" \
        : "+r"((d)[0]),"+r"((d)[1]) \
        : "r"((a)[0]),"r"((a)[1]),"r"((a)[2]),"r"((a)[3]), "r"(b0),"r"(b1))

__global__ __launch_bounds__(NTH, 3)
void tfm_mma_kernel(const int*   __restrict__ x,
                    const float* __restrict__ table,
                    const float* __restrict__ lw,
                    const float* __restrict__ lb,
                    const float* __restrict__ W0,
                    const float* __restrict__ W1,
                    float*       __restrict__ out)
{
    extern __shared__ char sm[];
    int*      idxr = (int*)(sm + O_IDX);        // [slot*80 + row*39 + k]
    float*    linA = (float*)(sm + O_LIN);      // [pair*80 + row*39 + k]
    float*    Pb   = (float*)(sm + O_PB);       // [pair*256 + wid*32 + lid]
    uint16_t* Ab   = (uint16_t*)(sm + O_A);     // [slot*128*SAH + row*SAH + k]
    uint16_t* Bb   = (uint16_t*)(sm + O_B);

    const int tid = threadIdx.x;
    const int wid = tid >> 5;
    const int lid = tid & 31;
    const int bid = blockIdx.x;
    const int np  = (PAIRS - bid + GRID - 1) / GRID;     // 9 or 10 pairs

    // ---- zero A slots + B (covers K pads) ----
    for (int t = tid; t < (2*128*SA + 160*SA) / 16; t += NTH)
        ((float4*)(sm + O_A))[t] = make_float4(0.f, 0.f, 0.f, 0.f);

    // ---- stage pair 0 (2 rows x 39 idx + lin) ----
    if (tid < 2 * NF) {
        int row = tid / NF, k = tid % NF;
        int xi = x[(2 * bid + row) * NF + k];
        idxr[row * NF + k] = xi;
        linA[row * NF + k] = lw[xi];
    }
    __syncthreads();

    // ---- build B once: row n = s*32 + j, fp16 ----
    for (int t = tid; t < 160 * NF; t += NTH) {
        int n = t / NF, k = t - n * NF;
        int s = n >> 5, j = n & 31;
        float w = (s < 2) ? W0[(s * 32 + j) * NF + k]
                          : W1[((s - 2) * 32 + j) * NF + k];
        Bb[n * SAH + k] = __half_as_ushort(__float2half_rn(w));
    }

    // A-build mapping: ar = row 0..127 (bh*64 + embed), kg = k-half
    const int ar = tid & 127;
    const int bh = ar >> 6;
    const int ai = ar & 63;
    const int kg = tid >> 7;
    const int k0 = kg * 20;
    const int kn = kg ? 19 : 20;

    // ---- build A pair 0 into slot 0 ----
    {
        uint32_t pk[10];
        #pragma unroll
        for (int p = 0; p < 10; p++) {
            int ka = k0 + 2*p, kb = ka + 1;
            float ea = (2*p     < kn) ? __ldg(table + (size_t)idxr[bh*NF + ka] * 64 + ai) : 0.f;
            float eb = (2*p + 1 < kn) ? __ldg(table + (size_t)idxr[bh*NF + kb] * 64 + ai) : 0.f;
            pk[p] = (uint32_t)__half_as_ushort(__float2half_rn(ea))
                  | ((uint32_t)__half_as_ushort(__float2half_rn(eb)) << 16);
        }
        uint32_t* ap = (uint32_t*)&Ab[ar * SAH + k0];
        #pragma unroll
        for (int p = 0; p < 10; p++) ap[p] = pk[p];
    }
    // ---- stage pair 1 into slot 1 ----
    if (np > 1 && tid < 2 * NF) {
        int row = tid / NF, k = tid % NF;
        int xi = x[(2 * (bid + GRID) + row) * NF + k];
        idxr[80 + row * NF + k] = xi;
        linA[80 + row * NF + k] = lw[xi];
    }
    __syncthreads();

    // warp tiling: wm = batch half, wj = rank octet
    const int wm = wid & 1;
    const int wj = wid >> 1;
    const uint32_t aOff  = (uint32_t)(wm*64 + (lid & 15)) * SA + (uint32_t)(lid >> 4) * 16u;
    const uint32_t aB0   = s2u(Ab) + aOff;
    const uint32_t aB1   = aB0 + 128u * SA;
    const uint32_t bBase = s2u(Bb) + (uint32_t)(wj*8 + (lid & 7)) * SA + (uint32_t)((lid >> 3) & 1) * 16u;

    for (int i = 0; i < np; i++) {
        const uint32_t aBase = (i & 1) ? aB1 : aB0;

        // ---- prefetch pair i+1 gathers (overlaps MMA) ----
        uint32_t pk[10];
        if (i + 1 < np) {
            const int* ib = idxr + ((i + 1) & 1) * 80 + bh * NF;
            #pragma unroll
            for (int p = 0; p < 10; p++) {
                int ka = k0 + 2*p, kb = ka + 1;
                float ea = (2*p     < kn) ? __ldg(table + (size_t)ib[ka] * 64 + ai) : 0.f;
                float eb = (2*p + 1 < kn) ? __ldg(table + (size_t)ib[kb] * 64 + ai) : 0.f;
                pk[p] = (uint32_t)__half_as_ushort(__float2half_rn(ea))
                      | ((uint32_t)__half_as_ushort(__float2half_rn(eb)) << 16);
            }
        }

        // ---- MMA: 5 segments x 4 m-tiles x 3 k-steps, f16 acc ----
        uint32_t acc[5][4][2];
        #pragma unroll
        for (int s = 0; s < 5; s++)
            #pragma unroll
            for (int mt = 0; mt < 4; mt++)
                acc[s][mt][0] = acc[s][mt][1] = 0u;

        #pragma unroll
        for (int ks = 0; ks < 3; ks++) {
            uint32_t bf[5][2];
            #pragma unroll
            for (int s = 0; s < 5; s++)
                LDSM2(bf[s], bBase + (uint32_t)s * (32u*SA) + (uint32_t)ks * 32u);
            #pragma unroll
            for (int mt = 0; mt < 4; mt++) {
                uint32_t af[4];
                LDSM4(af, aBase + (uint32_t)mt * (16u*SA) + (uint32_t)ks * 32u);
                #pragma unroll
                for (int s = 0; s < 5; s++)
                    MMAH(acc[s][mt], af, bf[s][0], bf[s][1]);
            }
        }

        // ---- stage pair i+2 (slot i&1, free after prefetch above) ----
        if (i + 2 < np && tid < 2 * NF) {
            int row = tid / NF, k = tid % NF;
            int xi = x[(2 * (bid + (i + 2) * GRID) + row) * NF + k];
            idxr[(i & 1) * 80 + row * NF + k] = xi;
            linA[(i + 2) * 80 + row * NF + k] = lw[xi];
        }

        // ---- store prefetched A into other slot ----
        if (i + 1 < np) {
            uint32_t* ap = (uint32_t*)&Ab[((i + 1) & 1) * 128 * SAH + ar * SAH + k0];
            #pragma unroll
            for (int p = 0; p < 10; p++) ap[p] = pk[p];
        }

        // ---- per-lane partial (fp32), one STS, no shfl ----
        float partial = 0.f;
        #pragma unroll
        for (int mt = 0; mt < 4; mt++)
            #pragma unroll
            for (int r = 0; r < 2; r++) {
                float2 d0 = __half22float2(*(const __half2*)&acc[0][mt][r]);
                float2 d1 = __half22float2(*(const __half2*)&acc[1][mt][r]);
                float2 d2 = __half22float2(*(const __half2*)&acc[2][mt][r]);
                float2 d3 = __half22float2(*(const __half2*)&acc[3][mt][r]);
                float2 d4 = __half22float2(*(const __half2*)&acc[4][mt][r]);
                partial += d0.x * d1.x + d2.x * d3.x * d4.x;
                partial += d0.y * d1.y + d2.y * d3.y * d4.y;
            }
        Pb[i * 256 + wid * 32 + lid] = partial;

        __syncthreads();   // A[alt] + idxr + Pb visible
    }

    // ---- final: one warp per output (pair, row) ----
    for (int o = wid; o < 2 * np; o += 8) {
        int pair = o >> 1, r = o & 1;
        const float* pb = Pb + pair * 256;
        float s = pb[(r    ) * 32 + lid] + pb[(r + 2) * 32 + lid]
                + pb[(r + 4) * 32 + lid] + pb[(r + 6) * 32 + lid];
        s += linA[pair * 80 + r * NF + lid];
        if (lid < NF - 32) s += linA[pair * 80 + r * NF + 32 + lid];
        #pragma unroll
        for (int off = 16; off > 0; off >>= 1)
            s += __shfl_down_sync(0xffffffffu, s, off);
        if (lid == 0) out[2 * (bid + pair * GRID) + r] = s + lb[0];
    }
}

extern "C" void kernel_launch(void* const* d_in, const int* in_sizes, int n_in,
                              void* d_out, int out_size)
{
    const int*   x     = (const int*)  d_in[0];
    const float* table = (const float*)d_in[1];
    const float* lw    = (const float*)d_in[2];
    const float* lb    = (const float*)d_in[3];
    const float* W0    = (const float*)d_in[4];
    const float* W1    = (const float*)d_in[5];
    float*       out   = (float*)d_out;
    (void)in_sizes; (void)n_in; (void)out_size;

    cudaFuncSetAttribute(tfm_mma_kernel, cudaFuncAttributeMaxDynamicSharedMemorySize, SMEM_TOTAL);
    tfm_mma_kernel<<<GRID, NTH, SMEM_TOTAL>>>(x, table, lw, lb, W0, W1, out);
}

// round 11
// speedup vs baseline: 5.7044x; 1.0103x over previous
#include <cuda_runtime.h>
#include <cuda_fp16.h>
#include <cstdint>

#define NF     39
#define BATCH  8192
#define PAIRS  4096
#define NTH    256
#define GRID   444                      // 148 SMs x 3 CTAs = one full wave
#define MAXP   10                       // max pairs per CTA

#define SA     112                      // row stride bytes (48 fp16 + pad)
#define SAH    56

#define WSCALE 128.0f                   // B pre-scale (power of 2, fp16-exact)
#define INV_P  (1.0f/16384.0f)          // 1/WSCALE^2
#define INV_T  (1.0f/2097152.0f)        // 1/WSCALE^3

// dynamic smem offsets (bytes)
#define O_IDX  0                        // int [2][80]
#define O_LIN  640                      // float [MAXP][80]
#define O_PB   3840                     // float [MAXP][8][32]
#define O_A    14080                    // u16 [2][128*SAH]  (2 x 14336 B)
#define O_B    42752                    // u16 [160*SAH]     (17920 B)
#define SMEM_TOTAL 60672

static __device__ __forceinline__ uint32_t s2u(const void* p){
    uint32_t a;
    asm("{ .reg .u64 t; cvta.to.shared.u64 t, %1; cvt.u32.u64 %0, t; }" : "=r"(a) : "l"(p));
    return a;
}
static __device__ __forceinline__ uint32_t pack_h2(float a, float b){
    __half2 h = __float22half2_rn(make_float2(a, b));
    return *(uint32_t*)&h;
}

#define LDSM4(r, a) \
    asm volatile("ldmatrix.sync.aligned.m8n8.x4.shared.b16 {%0,%1,%2,%3}, [%4];" \
        : "=r"((r)[0]),"=r"((r)[1]),"=r"((r)[2]),"=r"((r)[3]) : "r"(a))
#define LDSM2(r, a) \
    asm volatile("ldmatrix.sync.aligned.m8n8.x2.shared.b16 {%0,%1}, [%2];" \
        : "=r"((r)[0]),"=r"((r)[1]) : "r"(a))
#define MMAH(d, a, b0, b1) \
    asm volatile("mma.sync.aligned.m16n8k16.row.col.f16.f16.f16.f16 " \
        "{%0,%1},{%2,%3,%4,%5},{%6,%7},{%0,%1};" \
        : "+r"((d)[0]),"+r"((d)[1]) \
        : "r"((a)[0]),"r"((a)[1]),"r"((a)[2]),"r"((a)[3]), "r"(b0),"r"(b1))

__global__ __launch_bounds__(NTH, 3)
void tfm_mma_kernel(const int*   __restrict__ x,
                    const float* __restrict__ table,
                    const float* __restrict__ lw,
                    const float* __restrict__ lb,
                    const float* __restrict__ W0,
                    const float* __restrict__ W1,
                    float*       __restrict__ out)
{
    extern __shared__ char sm[];
    int*      idxr = (int*)(sm + O_IDX);        // [slot*80 + row*39 + k]
    float*    linA = (float*)(sm + O_LIN);      // [pair*80 + row*39 + k]
    float*    Pb   = (float*)(sm + O_PB);       // [pair*256 + wid*32 + lid]
    uint16_t* Ab   = (uint16_t*)(sm + O_A);     // [slot*128*SAH + row*SAH + k]
    uint16_t* Bb   = (uint16_t*)(sm + O_B);

    const int tid = threadIdx.x;
    const int wid = tid >> 5;
    const int lid = tid & 31;
    const int bid = blockIdx.x;
    const int np  = (PAIRS - bid + GRID - 1) / GRID;     // 9 or 10 pairs

    // ---- zero A slots + B (covers K pads) ----
    for (int t = tid; t < (2*128*SA + 160*SA) / 16; t += NTH)
        ((float4*)(sm + O_A))[t] = make_float4(0.f, 0.f, 0.f, 0.f);

    // ---- stage pair 0 ----
    if (tid < 2 * NF) {
        int row = tid / NF, k = tid % NF;
        int xi = x[(2 * bid + row) * NF + k];
        idxr[row * NF + k] = xi;
        linA[row * NF + k] = lw[xi];
    }
    __syncthreads();

    // ---- build B once: row n = s*32 + j, fp16, scaled by WSCALE ----
    for (int t = tid; t < 160 * NF; t += NTH) {
        int n = t / NF, k = t - n * NF;
        int s = n >> 5, j = n & 31;
        float w = (s < 2) ? W0[(s * 32 + j) * NF + k]
                          : W1[((s - 2) * 32 + j) * NF + k];
        Bb[n * SAH + k] = __half_as_ushort(__float2half_rn(w * WSCALE));
    }

    // A-build mapping: ar = row 0..127 (bh*64 + embed), kg = k-half
    const int ar = tid & 127;
    const int bh = ar >> 6;
    const int ai = ar & 63;
    const int kg = tid >> 7;
    const int k0 = kg * 20;
    const int kn = kg ? 19 : 20;

    // ---- build A pair 0 into slot 0 ----
    {
        uint32_t pk[10];
        #pragma unroll
        for (int p = 0; p < 10; p++) {
            int ka = k0 + 2*p, kb = ka + 1;
            float ea = (2*p     < kn) ? __ldg(table + (size_t)idxr[bh*NF + ka] * 64 + ai) : 0.f;
            float eb = (2*p + 1 < kn) ? __ldg(table + (size_t)idxr[bh*NF + kb] * 64 + ai) : 0.f;
            pk[p] = pack_h2(ea, eb);
        }
        uint2* ap = (uint2*)&Ab[ar * SAH + k0];
        #pragma unroll
        for (int p = 0; p < 5; p++) ap[p] = make_uint2(pk[2*p], pk[2*p+1]);
    }
    // ---- stage pair 1 into slot 1 ----
    if (np > 1 && tid < 2 * NF) {
        int row = tid / NF, k = tid % NF;
        int xi = x[(2 * (bid + GRID) + row) * NF + k];
        idxr[80 + row * NF + k] = xi;
        linA[80 + row * NF + k] = lw[xi];
    }
    __syncthreads();

    // warp tiling: wm = batch half, wj = rank octet
    const int wm = wid & 1;
    const int wj = wid >> 1;
    const uint32_t aOff  = (uint32_t)(wm*64 + (lid & 15)) * SA + (uint32_t)(lid >> 4) * 16u;
    const uint32_t aB0   = s2u(Ab) + aOff;
    const uint32_t aB1   = aB0 + 128u * SA;
    const uint32_t bBase = s2u(Bb) + (uint32_t)(wj*8 + (lid & 7)) * SA + (uint32_t)((lid >> 3) & 1) * 16u;

    for (int i = 0; i < np; i++) {
        const uint32_t aBase = (i & 1) ? aB1 : aB0;

        // ---- prefetch pair i+1 gathers (overlaps MMA) ----
        uint32_t pk[10];
        if (i + 1 < np) {
            const int* ib = idxr + ((i + 1) & 1) * 80 + bh * NF;
            #pragma unroll
            for (int p = 0; p < 10; p++) {
                int ka = k0 + 2*p, kb = ka + 1;
                float ea = (2*p     < kn) ? __ldg(table + (size_t)ib[ka] * 64 + ai) : 0.f;
                float eb = (2*p + 1 < kn) ? __ldg(table + (size_t)ib[kb] * 64 + ai) : 0.f;
                pk[p] = pack_h2(ea, eb);
            }
        }

        // ---- MMA: 5 segments x 4 m-tiles x 3 k-steps, f16 acc ----
        uint32_t acc[5][4][2];
        #pragma unroll
        for (int s = 0; s < 5; s++)
            #pragma unroll
            for (int mt = 0; mt < 4; mt++)
                acc[s][mt][0] = acc[s][mt][1] = 0u;

        #pragma unroll
        for (int ks = 0; ks < 3; ks++) {
            uint32_t bf[5][2];
            #pragma unroll
            for (int s = 0; s < 5; s++)
                LDSM2(bf[s], bBase + (uint32_t)s * (32u*SA) + (uint32_t)ks * 32u);
            #pragma unroll
            for (int mt = 0; mt < 4; mt++) {
                uint32_t af[4];
                LDSM4(af, aBase + (uint32_t)mt * (16u*SA) + (uint32_t)ks * 32u);
                #pragma unroll
                for (int s = 0; s < 5; s++)
                    MMAH(acc[s][mt], af, bf[s][0], bf[s][1]);
            }
        }

        // ---- stage pair i+2 (slot i&1, free after prefetch above) ----
        if (i + 2 < np && tid < 2 * NF) {
            int row = tid / NF, k = tid % NF;
            int xi = x[(2 * (bid + (i + 2) * GRID) + row) * NF + k];
            idxr[(i & 1) * 80 + row * NF + k] = xi;
            linA[(i + 2) * 80 + row * NF + k] = lw[xi];
        }

        // ---- store prefetched A into other slot (STS.64) ----
        if (i + 1 < np) {
            uint2* ap = (uint2*)&Ab[((i + 1) & 1) * 128 * SAH + ar * SAH + k0];
            #pragma unroll
            for (int p = 0; p < 5; p++) ap[p] = make_uint2(pk[2*p], pk[2*p+1]);
        }

        // ---- half2 epilogue: pair + triple accumulators, one STS ----
        {
            __half2 pair2 = __float2half2_rn(0.f);
            __half2 trip2 = __float2half2_rn(0.f);
            #pragma unroll
            for (int mt = 0; mt < 4; mt++)
                #pragma unroll
                for (int r = 0; r < 2; r++) {
                    __half2 d0 = *(const __half2*)&acc[0][mt][r];
                    __half2 d1 = *(const __half2*)&acc[1][mt][r];
                    __half2 d2 = *(const __half2*)&acc[2][mt][r];
                    __half2 d3 = *(const __half2*)&acc[3][mt][r];
                    __half2 d4 = *(const __half2*)&acc[4][mt][r];
                    pair2 = __hfma2(d0, d1, pair2);
                    trip2 = __hfma2(__hmul2(d2, d3), d4, trip2);
                }
            float2 pp = __half22float2(pair2);
            float2 qq = __half22float2(trip2);
            Pb[i * 256 + wid * 32 + lid] =
                (pp.x + pp.y) * INV_P + (qq.x + qq.y) * INV_T;
        }

        __syncthreads();   // A[alt] + idxr + Pb visible
    }

    // ---- final: one warp per output (pair, row) ----
    for (int o = wid; o < 2 * np; o += 8) {
        int pair = o >> 1, r = o & 1;
        const float* pb = Pb + pair * 256;
        float s = pb[(r    ) * 32 + lid] + pb[(r + 2) * 32 + lid]
                + pb[(r + 4) * 32 + lid] + pb[(r + 6) * 32 + lid];
        s += linA[pair * 80 + r * NF + lid];
        if (lid < NF - 32) s += linA[pair * 80 + r * NF + 32 + lid];
        #pragma unroll
        for (int off = 16; off > 0; off >>= 1)
            s += __shfl_down_sync(0xffffffffu, s, off);
        if (lid == 0) out[2 * (bid + pair * GRID) + r] = s + lb[0];
    }
}

extern "C" void kernel_launch(void* const* d_in, const int* in_sizes, int n_in,
                              void* d_out, int out_size)
{
    const int*   x     = (const int*)  d_in[0];
    const float* table = (const float*)d_in[1];
    const float* lw    = (const float*)d_in[2];
    const float* lb    = (const float*)d_in[3];
    const float* W0    = (const float*)d_in[4];
    const float* W1    = (const float*)d_in[5];
    float*       out   = (float*)d_out;
    (void)in_sizes; (void)n_in; (void)out_size;

    cudaFuncSetAttribute(tfm_mma_kernel, cudaFuncAttributeMaxDynamicSharedMemorySize, SMEM_TOTAL);
    tfm_mma_kernel<<<GRID, NTH, SMEM_TOTAL>>>(x, table, lw, lb, W0, W1, out);
}